// round 16
// baseline (speedup 1.0000x reference)
#include <cuda_runtime.h>
#include <cuda_fp16.h>
#include <math.h>
#include <stdint.h>

#define L_SEQ   2048
#define NBATCH  2
#define HIDDEN  2048
#define NH      64
#define PDIM    64
#define NDIM    128
#define CS      64
#define NC      32
#define D_INNER 4096
#define CONV_DIM 4352
#define PROJ    8512
#define PROJ_PAD 8576   // 67 * 128

// ---------------- scratch (device globals: allocation-free) ----------------
__device__ float  g_proj  [NBATCH*L_SEQ*PROJ];
__device__ float  g_xc    [NBATCH*L_SEQ*CONV_DIM];
__device__ float  g_dtsp  [NBATCH*NH*L_SEQ];          // [b][h][l] (transposed)
__device__ float  g_Acum  [NBATCH*NH*NC*CS];
__device__ float  g_Gt    [NBATCH*NC*CS*CS];
__device__ __half g_states[NBATCH*NC*NH*PDIM*NDIM];
__device__ float  g_y     [NBATCH*L_SEQ*D_INNER];
// fp16 GEMM operands
__device__ __half g_hsh  [NBATCH*L_SEQ*HIDDEN];
__device__ __half g_Wih  [PROJ_PAD*HIDDEN];
__device__ __half g_Woh  [HIDDEN*D_INNER];
__device__ __half g_yh   [NBATCH*L_SEQ*D_INNER];

// ---------------- helpers ---------------------------------------------------
__device__ __forceinline__ float f2tf(float f) {
    unsigned r;
    asm("cvt.rna.tf32.f32 %0, %1;" : "=r"(r) : "f"(f));
    return __uint_as_float(r);
}

__device__ __forceinline__ void mma_tf32(
    float* c, const unsigned* a, const unsigned* b)
{
    asm volatile(
        "mma.sync.aligned.m16n8k8.row.col.f32.tf32.tf32.f32 "
        "{%0,%1,%2,%3}, {%4,%5,%6,%7}, {%8,%9}, {%0,%1,%2,%3};"
        : "+f"(c[0]), "+f"(c[1]), "+f"(c[2]), "+f"(c[3])
        : "r"(a[0]), "r"(a[1]), "r"(a[2]), "r"(a[3]),
          "r"(b[0]), "r"(b[1]));
}

__device__ __forceinline__ void mma_f16(
    float* c, const unsigned* a, unsigned b0, unsigned b1)
{
    asm volatile(
        "mma.sync.aligned.m16n8k16.row.col.f32.f16.f16.f32 "
        "{%0,%1,%2,%3}, {%4,%5,%6,%7}, {%8,%9}, {%0,%1,%2,%3};"
        : "+f"(c[0]), "+f"(c[1]), "+f"(c[2]), "+f"(c[3])
        : "r"(a[0]), "r"(a[1]), "r"(a[2]), "r"(a[3]),
          "r"(b0), "r"(b1));
}

__device__ __forceinline__ void ldsm4(unsigned* r, uint32_t addr) {
    asm volatile(
        "ldmatrix.sync.aligned.m8n8.x4.shared.b16 {%0,%1,%2,%3}, [%4];"
        : "=r"(r[0]), "=r"(r[1]), "=r"(r[2]), "=r"(r[3]) : "r"(addr));
}

__device__ __forceinline__ void cp16(unsigned smem, const void* g) {
    asm volatile("cp.async.cg.shared.global [%0], [%1], 16;\n" :: "r"(smem), "l"(g));
}
__device__ __forceinline__ void cp_commit() {
    asm volatile("cp.async.commit_group;\n");
}
template<int N> __device__ __forceinline__ void cp_wait() {
    asm volatile("cp.async.wait_group %0;\n" :: "n"(N));
}

// ---------------- convert kernels (fp32 -> fp16) ----------------------------
__global__ __launch_bounds__(256) void tohalf_kernel(
    const float* __restrict__ src, __half* __restrict__ dst, int n)
{
    int i = blockIdx.x * 256 + threadIdx.x;
    if (i < n) dst[i] = __float2half(src[i]);
}
__global__ __launch_bounds__(256) void tohalf_pad_kernel(
    const float* __restrict__ src, __half* __restrict__ dst, int rows, int rows_pad, int cols)
{
    int i = blockIdx.x * 256 + threadIdx.x;
    if (i < rows_pad * cols) {
        int r = i / cols;
        dst[i] = (r < rows) ? __float2half(src[i]) : __float2half(0.f);
    }
}

// ---------------- persistent pipelined fp16 NT GEMM -------------------------
#define STAGES 3
#define SSTRIDE_H (128*64)
#define GEMM_THREADS 128
__global__ __launch_bounds__(GEMM_THREADS, 2) void gemm_f16_pipe(
    const __half* __restrict__ A, const __half* __restrict__ B, float* __restrict__ C,
    int M, int N, int K, int lda, int ldb, int ldc)
{
    extern __shared__ __half smh[];
    __half* As = smh;
    __half* Bs = smh + STAGES * SSTRIDE_H;
    int tid = threadIdx.x;
    int warp = tid >> 5, lane = tid & 31;
    int g = lane >> 2, tg = lane & 3;
    int wm = (warp & 1) * 64, wn = (warp >> 1) * 64;

    int grp = lane >> 3, rin = lane & 7;
    int rowF = (grp & 1) * 8 + rin;
    int bitF = grp >> 1;

    unsigned asBase = (unsigned)__cvta_generic_to_shared(As);
    unsigned bsBase = (unsigned)__cvta_generic_to_shared(Bs);

    const int KT = K >> 6;
    const int ntn = (N + 127) >> 7;
    const int ntiles = (M >> 7) * ntn;

    for (int tile = blockIdx.x; tile < ntiles; tile += gridDim.x) {
        int bm = (tile / ntn) * 128;
        int bn = (tile % ntn) * 128;

        float acc[4][8][4];
#pragma unroll
        for (int mi = 0; mi < 4; mi++)
#pragma unroll
            for (int ni = 0; ni < 8; ni++)
#pragma unroll
                for (int j = 0; j < 4; j++) acc[mi][ni][j] = 0.f;

        auto issue_stage = [&](int stage, int kt) {
            int kk = kt << 6;
            unsigned aS = asBase + (unsigned)(stage * SSTRIDE_H) * 2u;
            unsigned bS = bsBase + (unsigned)(stage * SSTRIDE_H) * 2u;
#pragma unroll
            for (int i = 0; i < 8; i++) {
                int id = tid + i * GEMM_THREADS;
                int row = id >> 3, c16 = id & 7;
                int pc = c16 ^ (row & 7);
                unsigned off = (unsigned)(row * 128 + pc * 16);
                cp16(aS + off, A + (size_t)(bm + row) * lda + kk + c16 * 8);
                cp16(bS + off, B + (size_t)(bn + row) * ldb + kk + c16 * 8);
            }
            cp_commit();
        };

        issue_stage(0, 0);
        if (KT > 1) issue_stage(1, 1);

        for (int kt = 0; kt < KT; kt++) {
            if (kt < KT - 1) cp_wait<1>(); else cp_wait<0>();
            __syncthreads();
            if (kt + 2 < KT) issue_stage((kt + 2) % STAGES, kt + 2);

            unsigned aS = asBase + (unsigned)((kt % STAGES) * SSTRIDE_H) * 2u;
            unsigned bS = bsBase + (unsigned)((kt % STAGES) * SSTRIDE_H) * 2u;
#pragma unroll
            for (int ks = 0; ks < 4; ks++) {
                unsigned af[4][4], bf[4][4];
#pragma unroll
                for (int mi = 0; mi < 4; mi++) {
                    unsigned addr = aS
                        + (unsigned)((wm + mi * 16 + rowF) * 128)
                        + (unsigned)((((2*ks + bitF) ^ rin) & 7) << 4);
                    ldsm4(af[mi], addr);
                }
#pragma unroll
                for (int np = 0; np < 4; np++) {
                    unsigned addr = bS
                        + (unsigned)((wn + np * 16 + rowF) * 128)
                        + (unsigned)((((2*ks + bitF) ^ rin) & 7) << 4);
                    ldsm4(bf[np], addr);
                }
#pragma unroll
                for (int mi = 0; mi < 4; mi++) {
#pragma unroll
                    for (int np = 0; np < 4; np++) {
                        mma_f16(acc[mi][np*2    ], af[mi], bf[np][0], bf[np][2]);
                        mma_f16(acc[mi][np*2 + 1], af[mi], bf[np][1], bf[np][3]);
                    }
                }
            }
        }

#pragma unroll
        for (int mi = 0; mi < 4; mi++) {
            int row0 = bm + wm + mi * 16 + g;
#pragma unroll
            for (int ni = 0; ni < 8; ni++) {
                int col = bn + wn + ni * 8 + 2 * tg;
                if (col < N) {
                    *(float2*)(C + (size_t)row0 * ldc + col) =
                        make_float2(acc[mi][ni][0], acc[mi][ni][1]);
                    *(float2*)(C + (size_t)(row0 + 8) * ldc + col) =
                        make_float2(acc[mi][ni][2], acc[mi][ni][3]);
                }
            }
        }
        __syncthreads();
    }
}

// -------- smem-tiled causal depthwise conv (K=4) + bias + SiLU -------------
#define CVT 256
__global__ __launch_bounds__(256) void conv_silu_kernel(
    const float* __restrict__ cw, const float* __restrict__ cb)
{
    extern __shared__ float sh[];          // [(CVT+3)][68]
    int tid = threadIdx.x;
    int c0 = blockIdx.x * 64;
    int l0 = blockIdx.y * CVT;
    int b  = blockIdx.z;

    for (int idx = tid; idx < (CVT + 3) * 64; idx += 256) {
        int r = idx >> 6, c = idx & 63;
        int gl = l0 + r - 3;
        float v = 0.f;
        if (gl >= 0)
            v = g_proj[((size_t)(b*L_SEQ + gl))*PROJ + D_INNER + c0 + c];
        sh[r*68 + c] = v;
    }
    __syncthreads();

    int c = tid & 63, lg = tid >> 6;
    int ch = c0 + c;
    float w0 = cw[ch*4 + 0], w1 = cw[ch*4 + 1];
    float w2 = cw[ch*4 + 2], w3 = cw[ch*4 + 3];
    float bias = cb[ch];
#pragma unroll 4
    for (int i = 0; i < 64; i++) {
        int l = lg*64 + i;
        const float* r = sh + l*68 + c;
        float acc = bias + r[0]*w0 + r[68]*w1 + r[136]*w2 + r[204]*w3;
        acc = acc / (1.f + __expf(-acc));
        g_xc[((size_t)(b*L_SEQ + l0 + l))*CONV_DIM + ch] = acc;
    }
}

// ------- dt softplus + per-64-chunk inclusive cumsum of dt*A ---------------
// g_dtsp layout: [b][h][l]  (coalesced write here, coalesced read in chunk_fwd)
__global__ __launch_bounds__(256) void dtscan_kernel(
    const float* __restrict__ dt_bias, const float* __restrict__ A_log)
{
    __shared__ float s[256];
    int z = blockIdx.x;
    int q = z & 7, h = (z >> 3) & 63, b = z >> 9;
    int t = threadIdx.x;
    int gl = q*256 + t;
    float raw = g_proj[((size_t)(b*L_SEQ + gl))*PROJ + D_INNER + CONV_DIM + h] + dt_bias[h];
    float dts = (raw > 20.f) ? raw : log1pf(__expf(raw));
    g_dtsp[((size_t)(b*NH + h))*L_SEQ + gl] = dts;
    s[t] = -dts * __expf(A_log[h]);
    __syncthreads();
    for (int off = 1; off < 64; off <<= 1) {
        float v = ((t & 63) >= off) ? s[t - off] : 0.f;
        __syncthreads();
        s[t] += v;
        __syncthreads();
    }
    int c = gl >> 6;
    g_Acum[((size_t)((b*NH + h)*NC + c))*CS + (gl & 63)] = s[t];
}

// -------- G[l][s] = C[l]·B[s] per (b,chunk), tf32 mma ----------------------
__global__ __launch_bounds__(256) void gt_kernel()
{
    extern __shared__ float smg[];
    float* Ct = smg;              // [64][132]
    float* Bt = smg + 64*132;
    int z = blockIdx.x;
    int c = z & 31, b = z >> 5;
    int tid = threadIdx.x;
    size_t t0 = (size_t)(b*L_SEQ + c*CS);
    {
        int n = tid & 127, rg = tid >> 7;
#pragma unroll
        for (int i = 0; i < 32; i++) {
            int row = rg*32 + i;
            Bt[row*132 + n] = f2tf(g_xc[(t0 + row)*CONV_DIM + D_INNER + n]);
            Ct[row*132 + n] = f2tf(g_xc[(t0 + row)*CONV_DIM + D_INNER + NDIM + n]);
        }
    }
    __syncthreads();

    int warp = tid >> 5, lane = tid & 31;
    int g = lane >> 2, tg = lane & 3;
    int wm = (warp & 3) * 16;
    int wn = (warp >> 2) * 32;

    float acc[4][4];
#pragma unroll
    for (int ni = 0; ni < 4; ni++)
#pragma unroll
        for (int j = 0; j < 4; j++) acc[ni][j] = 0.f;

#pragma unroll
    for (int ks = 0; ks < 16; ks++) {
        int k0 = ks*8 + tg;
        unsigned a[4];
        a[0] = __float_as_uint(Ct[(wm + g    )*132 + k0    ]);
        a[1] = __float_as_uint(Ct[(wm + g + 8)*132 + k0    ]);
        a[2] = __float_as_uint(Ct[(wm + g    )*132 + k0 + 4]);
        a[3] = __float_as_uint(Ct[(wm + g + 8)*132 + k0 + 4]);
#pragma unroll
        for (int ni = 0; ni < 4; ni++) {
            unsigned bb[2];
            bb[0] = __float_as_uint(Bt[(wn + ni*8 + g)*132 + k0    ]);
            bb[1] = __float_as_uint(Bt[(wn + ni*8 + g)*132 + k0 + 4]);
            mma_tf32(acc[ni], a, bb);
        }
    }

    float* gout = g_Gt + (size_t)(b*NC + c)*CS*CS;
#pragma unroll
    for (int ni = 0; ni < 4; ni++) {
        int col = wn + ni*8 + 2*tg;
        *(float2*)(gout + (wm + g    )*CS + col) = make_float2(acc[ni][0], acc[ni][1]);
        *(float2*)(gout + (wm + g + 8)*CS + col) = make_float2(acc[ni][2], acc[ni][3]);
    }
}

// ---------------- fused chunk forward: Y_diag (+D*x) and states (fp16) -----
__global__ __launch_bounds__(256) void chunk_fwd_kernel(const float* __restrict__ Dp)
{
    extern __shared__ float smc[];
    float* XdtT = smc;             // [64][68]
    float* W    = smc + 64*68;     // [64][68]
    float* BT   = smc + 2*64*68;   // [128][68]
    float* Acs  = smc + 2*64*68 + 128*68;
    float* dts  = Acs + 64;
    float* dec  = dts + 64;

    int z = blockIdx.x;
    int h = z & 63, c = (z >> 6) & 31, b = z >> 11;
    int tid = threadIdx.x;
    size_t t0 = (size_t)(b*L_SEQ + c*CS);

    if (tid < 64) {
        Acs[tid] = g_Acum[((size_t)((b*NH + h)*NC + c))*CS + tid];
        dts[tid] = g_dtsp[((size_t)(b*NH + h))*L_SEQ + c*CS + tid];
    }
    __syncthreads();
    if (tid < 64) dec[tid] = __expf(Acs[63] - Acs[tid]);

    {
        int p = tid & 63, lg = tid >> 6;
#pragma unroll
        for (int i = 0; i < 16; i++) {
            int l = lg*16 + i;
            float v = g_xc[(t0 + l)*CONV_DIM + h*64 + p] * dts[l];
            XdtT[p*68 + l] = f2tf(v);
        }
    }
    {
        int l = tid >> 2, sb = tid & 3;
        const float* grow = g_Gt + (size_t)(b*NC + c)*CS*CS + l*CS;
        float al = Acs[l];
        float dg = Dp[h] / fmaxf(dts[l], 1e-30f);
#pragma unroll
        for (int i = 0; i < 16; i++) {
            int s = sb*16 + i;
            float wv;
            if (s < l)       wv = f2tf(grow[s] * __expf(al - Acs[s]));
            else if (s == l) wv = f2tf(grow[s] + dg);
            else             wv = 0.f;
            W[l*68 + s] = wv;
        }
    }
    __syncthreads();
    {
        int n = tid & 127, lg = tid >> 7;
#pragma unroll
        for (int i = 0; i < 32; i++) {
            int l = lg*32 + i;
            float v = g_xc[(t0 + l)*CONV_DIM + D_INNER + n] * dec[l];
            BT[n*68 + l] = f2tf(v);
        }
    }
    __syncthreads();

    int warp = tid >> 5, lane = tid & 31;
    int g = lane >> 2, tg = lane & 3;

    {
        int wm = (warp & 3) * 16, wn = (warp >> 2) * 32;
        float acc[4][4];
#pragma unroll
        for (int ni = 0; ni < 4; ni++)
#pragma unroll
            for (int j = 0; j < 4; j++) acc[ni][j] = 0.f;
#pragma unroll
        for (int ks = 0; ks < 8; ks++) {
            int k0 = ks*8 + tg;
            unsigned a[4];
            a[0] = __float_as_uint(W[(wm + g    )*68 + k0    ]);
            a[1] = __float_as_uint(W[(wm + g + 8)*68 + k0    ]);
            a[2] = __float_as_uint(W[(wm + g    )*68 + k0 + 4]);
            a[3] = __float_as_uint(W[(wm + g + 8)*68 + k0 + 4]);
#pragma unroll
            for (int ni = 0; ni < 4; ni++) {
                unsigned bb[2];
                bb[0] = __float_as_uint(XdtT[(wn + ni*8 + g)*68 + k0    ]);
                bb[1] = __float_as_uint(XdtT[(wn + ni*8 + g)*68 + k0 + 4]);
                mma_tf32(acc[ni], a, bb);
            }
        }
        int r0 = wm + g, r1 = wm + g + 8;
#pragma unroll
        for (int ni = 0; ni < 4; ni++) {
            int col = wn + ni*8 + 2*tg;
            *(float2*)(g_y + (t0 + r0)*D_INNER + h*64 + col) =
                make_float2(acc[ni][0], acc[ni][1]);
            *(float2*)(g_y + (t0 + r1)*D_INNER + h*64 + col) =
                make_float2(acc[ni][2], acc[ni][3]);
        }
    }

    {
        int wm = (warp & 3) * 16, wn = (warp >> 2) * 64;
        float acc[8][4];
#pragma unroll
        for (int ni = 0; ni < 8; ni++)
#pragma unroll
            for (int j = 0; j < 4; j++) acc[ni][j] = 0.f;
#pragma unroll
        for (int ks = 0; ks < 8; ks++) {
            int k0 = ks*8 + tg;
            unsigned a[4];
            a[0] = __float_as_uint(XdtT[(wm + g    )*68 + k0    ]);
            a[1] = __float_as_uint(XdtT[(wm + g + 8)*68 + k0    ]);
            a[2] = __float_as_uint(XdtT[(wm + g    )*68 + k0 + 4]);
            a[3] = __float_as_uint(XdtT[(wm + g + 8)*68 + k0 + 4]);
#pragma unroll
            for (int ni = 0; ni < 8; ni++) {
                unsigned bb[2];
                bb[0] = __float_as_uint(BT[(wn + ni*8 + g)*68 + k0    ]);
                bb[1] = __float_as_uint(BT[(wn + ni*8 + g)*68 + k0 + 4]);
                mma_tf32(acc[ni], a, bb);
            }
        }
        __half* sb = g_states + ((size_t)((b*NC + c)*NH + h))*PDIM*NDIM;
        int r0 = wm + g, r1 = wm + g + 8;
#pragma unroll
        for (int ni = 0; ni < 8; ni++) {
            int col = wn + ni*8 + 2*tg;
            *(__half2*)(sb + (size_t)r0*NDIM + col) =
                __floats2half2_rn(acc[ni][0], acc[ni][1]);
            *(__half2*)(sb + (size_t)r1*NDIM + col) =
                __floats2half2_rn(acc[ni][2], acc[ni][3]);
        }
    }
}

// ---- fused inter-chunk scan + contribution: one block per (b,h) -----------
// Carry state [p=64][n=128] lives in registers (32 fp32/thread); per chunk:
// stage Cs + Pv(tf32 carry), mma Y_off = Cs @ Pv^T, y += e^Acum * acc,
// then carry = carry*exp(dal) + states[c] (fp16).
__global__ __launch_bounds__(256) void scan_yoff_kernel()
{
    extern __shared__ float smo[];
    float* Cs  = smo;             // [64][132]
    float* Pv  = smo + 64*132;    // [64][132]
    float* Acs = smo + 2*64*132;  // [64]
    int z = blockIdx.x;           // b*NH + h
    int h = z & 63, b = z >> 6;
    int tid = threadIdx.x;

    int n = tid & 127, rg = tid >> 7;   // rows rg*32 + i
    float cr[32];
#pragma unroll
    for (int i = 0; i < 32; i++) cr[i] = 0.f;

    int warp = tid >> 5, lane = tid & 31;
    int g = lane >> 2, tg = lane & 3;
    int wm = (warp & 3) * 16;
    int wn = (warp >> 2) * 32;

    for (int c = 0; c < NC; c++) {
        size_t t0 = (size_t)(b*L_SEQ + c*CS);
        // phase 1: stage Cs(c), Pv(carry before c), Acs(c)
        if (tid < 64) Acs[tid] = g_Acum[((size_t)((b*NH + h)*NC + c))*CS + tid];
#pragma unroll
        for (int i = 0; i < 32; i++) {
            int row = rg*32 + i;
            Cs[row*132 + n] = f2tf(g_xc[(t0 + row)*CONV_DIM + D_INNER + NDIM + n]);
            Pv[row*132 + n] = f2tf(cr[i]);
        }
        __syncthreads();

        // phase 2: mma + y update + carry update
        float acc[4][4];
#pragma unroll
        for (int ni = 0; ni < 4; ni++)
#pragma unroll
            for (int j = 0; j < 4; j++) acc[ni][j] = 0.f;
#pragma unroll
        for (int ks = 0; ks < 16; ks++) {
            int k0 = ks*8 + tg;
            unsigned a[4];
            a[0] = __float_as_uint(Cs[(wm + g    )*132 + k0    ]);
            a[1] = __float_as_uint(Cs[(wm + g + 8)*132 + k0    ]);
            a[2] = __float_as_uint(Cs[(wm + g    )*132 + k0 + 4]);
            a[3] = __float_as_uint(Cs[(wm + g + 8)*132 + k0 + 4]);
#pragma unroll
            for (int ni = 0; ni < 4; ni++) {
                unsigned bb[2];
                bb[0] = __float_as_uint(Pv[(wn + ni*8 + g)*132 + k0    ]);
                bb[1] = __float_as_uint(Pv[(wn + ni*8 + g)*132 + k0 + 4]);
                mma_tf32(acc[ni], a, bb);
            }
        }
        float e0 = __expf(Acs[wm + g]);
        float e1 = __expf(Acs[wm + g + 8]);
#pragma unroll
        for (int ni = 0; ni < 4; ni++) {
            int col = wn + ni*8 + 2*tg;
            float* y0 = g_y + (t0 + wm + g)*D_INNER + h*64 + col;
            float* y1 = g_y + (t0 + wm + g + 8)*D_INNER + h*64 + col;
            float2 v0 = *(float2*)y0;
            float2 v1 = *(float2*)y1;
            v0.x += e0*acc[ni][0]; v0.y += e0*acc[ni][1];
            v1.x += e1*acc[ni][2]; v1.y += e1*acc[ni][3];
            *(float2*)y0 = v0;
            *(float2*)y1 = v1;
        }
        // carry update (registers only; Pv rewritten next iteration)
        {
            float edal = __expf(Acs[63]);
            const __half* sb = g_states + ((size_t)((b*NC + c)*NH + h))*PDIM*NDIM;
#pragma unroll
            for (int i = 0; i < 32; i++) {
                int row = rg*32 + i;
                cr[i] = cr[i]*edal + __half2float(sb[(size_t)row*NDIM + n]);
            }
        }
        __syncthreads();   // all reads of Cs/Pv/Acs done before next stage
    }
}

// ---------------- gated RMSNorm (writes fp16 output for out-proj) ----------
__global__ __launch_bounds__(256) void norm_kernel(const float* __restrict__ norm_w)
{
    __shared__ float gs[D_INNER];
    __shared__ float red[8];
    int t = blockIdx.x;
    int tid = threadIdx.x;
    const float* zrow = g_proj + (size_t)t * PROJ;
    const float* yrow = g_y + (size_t)t * D_INNER;
    __half* orow = g_yh + (size_t)t * D_INNER;
    float sum = 0.f;
    for (int i = tid; i < D_INNER; i += 256) {
        float zv = zrow[i];
        float g = yrow[i] * (zv / (1.f + __expf(-zv)));
        gs[i] = g;
        sum += g*g;
    }
#pragma unroll
    for (int o = 16; o; o >>= 1) sum += __shfl_xor_sync(0xffffffffu, sum, o);
    if ((tid & 31) == 0) red[tid >> 5] = sum;
    __syncthreads();
    if (tid < 8) {
        float v = red[tid];
#pragma unroll
        for (int o = 4; o; o >>= 1) v += __shfl_xor_sync(0xffu, v, o);
        if (tid == 0) red[0] = v;
    }
    __syncthreads();
    float r = rsqrtf(red[0] / (float)D_INNER + 1e-5f);
    for (int i = tid; i < D_INNER; i += 256)
        orow[i] = __float2half(gs[i] * r * norm_w[i]);
}

// ---------------- launch ---------------------------------------------------
extern "C" void kernel_launch(void* const* d_in, const int* in_sizes, int n_in,
                              void* d_out, int out_size)
{
    const float* hs      = (const float*)d_in[0];
    const float* W_in    = (const float*)d_in[1];
    const float* conv_w  = (const float*)d_in[2];
    const float* conv_b  = (const float*)d_in[3];
    const float* dt_bias = (const float*)d_in[4];
    const float* A_log   = (const float*)d_in[5];
    const float* Dp      = (const float*)d_in[6];
    const float* norm_w  = (const float*)d_in[7];
    const float* W_out   = (const float*)d_in[8];
    float* out = (float*)d_out;

    float *proj;
    __half *hsh, *Wih, *Woh, *yh;
    cudaGetSymbolAddress((void**)&proj, g_proj);
    cudaGetSymbolAddress((void**)&hsh,  g_hsh);
    cudaGetSymbolAddress((void**)&Wih,  g_Wih);
    cudaGetSymbolAddress((void**)&Woh,  g_Woh);
    cudaGetSymbolAddress((void**)&yh,   g_yh);

    const int gemmsm  = STAGES * 2 * SSTRIDE_H * (int)sizeof(__half);       // 98,304 B
    const int convsm  = (CVT + 3) * 68 * (int)sizeof(float);                // 70,448 B
    const int gtsm    = 2 * 64 * 132 * (int)sizeof(float);                  // 67,584 B
    const int chunksm = (2*64*68 + 128*68 + 3*64) * (int)sizeof(float);
    const int syosm   = (2*64*132 + 64) * (int)sizeof(float);               // 67,840 B
    cudaFuncSetAttribute(gemm_f16_pipe,    cudaFuncAttributeMaxDynamicSharedMemorySize, gemmsm);
    cudaFuncSetAttribute(conv_silu_kernel, cudaFuncAttributeMaxDynamicSharedMemorySize, convsm);
    cudaFuncSetAttribute(gt_kernel,        cudaFuncAttributeMaxDynamicSharedMemorySize, gtsm);
    cudaFuncSetAttribute(chunk_fwd_kernel, cudaFuncAttributeMaxDynamicSharedMemorySize, chunksm);
    cudaFuncSetAttribute(scan_yoff_kernel, cudaFuncAttributeMaxDynamicSharedMemorySize, syosm);

    const int M = NBATCH * L_SEQ;   // 4096 tokens
    const int NBLK = 296;           // persistent grid

    // 0) convert operands to fp16
    {
        int n1 = M * HIDDEN;
        tohalf_kernel<<<(n1 + 255)/256, 256>>>(hs, hsh, n1);
        int n2 = PROJ_PAD * HIDDEN;
        tohalf_pad_kernel<<<(n2 + 255)/256, 256>>>(W_in, Wih, PROJ, PROJ_PAD, HIDDEN);
        int n3 = HIDDEN * D_INNER;
        tohalf_kernel<<<(n3 + 255)/256, 256>>>(W_out, Woh, n3);
    }

    // 1) in-proj
    gemm_f16_pipe<<<NBLK, GEMM_THREADS, gemmsm>>>(
        hsh, Wih, proj, M, PROJ, HIDDEN, HIDDEN, HIDDEN, PROJ);

    // 2) causal conv + SiLU (smem-tiled)
    conv_silu_kernel<<<dim3(CONV_DIM/64, L_SEQ/CVT, NBATCH), 256, convsm>>>(conv_w, conv_b);

    // 3) dt softplus + per-64-chunk cumsum (transposed dtsp)
    dtscan_kernel<<<NBATCH*NH*8, 256>>>(dt_bias, A_log);

    // 4) G[l][s] per (b,chunk) (tf32 mma)
    gt_kernel<<<NBATCH*NC, 256, gtsm>>>();

    // 5) fused Y_diag (+D*x) and per-chunk states (fp16 states)
    chunk_fwd_kernel<<<NBATCH*NC*NH, 256, chunksm>>>(Dp);

    // 6) fused inter-chunk scan + contribution (register carry)
    scan_yoff_kernel<<<NBATCH*NH, 256, syosm>>>();

    // 7) gated RMSNorm (emits fp16 y)
    norm_kernel<<<M, 256>>>(norm_w);

    // 8) out-proj
    gemm_f16_pipe<<<NBLK, GEMM_THREADS, gemmsm>>>(
        yh, Woh, out, M, HIDDEN, D_INNER, D_INNER, D_INNER, HIDDEN);
}

// round 17
// speedup vs baseline: 1.5198x; 1.5198x over previous
#include <cuda_runtime.h>
#include <cuda_fp16.h>
#include <math.h>
#include <stdint.h>

#define L_SEQ   2048
#define NBATCH  2
#define HIDDEN  2048
#define NH      64
#define PDIM    64
#define NDIM    128
#define CS      64
#define NC      32
#define D_INNER 4096
#define CONV_DIM 4352
#define PROJ    8512
#define PROJ_PAD 8576   // 67 * 128

// ---------------- scratch (device globals: allocation-free) ----------------
__device__ float  g_proj  [NBATCH*L_SEQ*PROJ];
__device__ float  g_xc    [NBATCH*L_SEQ*CONV_DIM];
__device__ float  g_dtsp  [NBATCH*NH*L_SEQ];          // [b][h][l] (coalesced)
__device__ float  g_Acum  [NBATCH*NH*NC*CS];
__device__ float  g_Gt    [NBATCH*NC*CS*CS];
__device__ __half g_states[NBATCH*NC*NH*PDIM*NDIM];
__device__ __half g_prev  [NBATCH*NC*NH*PDIM*NDIM];
__device__ float  g_y     [NBATCH*L_SEQ*D_INNER];
// fp16 GEMM operands
__device__ __half g_hsh  [NBATCH*L_SEQ*HIDDEN];
__device__ __half g_Wih  [PROJ_PAD*HIDDEN];
__device__ __half g_Woh  [HIDDEN*D_INNER];
__device__ __half g_yh   [NBATCH*L_SEQ*D_INNER];

// ---------------- helpers ---------------------------------------------------
__device__ __forceinline__ float f2tf(float f) {
    unsigned r;
    asm("cvt.rna.tf32.f32 %0, %1;" : "=r"(r) : "f"(f));
    return __uint_as_float(r);
}

__device__ __forceinline__ void mma_tf32(
    float* c, const unsigned* a, const unsigned* b)
{
    asm volatile(
        "mma.sync.aligned.m16n8k8.row.col.f32.tf32.tf32.f32 "
        "{%0,%1,%2,%3}, {%4,%5,%6,%7}, {%8,%9}, {%0,%1,%2,%3};"
        : "+f"(c[0]), "+f"(c[1]), "+f"(c[2]), "+f"(c[3])
        : "r"(a[0]), "r"(a[1]), "r"(a[2]), "r"(a[3]),
          "r"(b[0]), "r"(b[1]));
}

__device__ __forceinline__ void mma_f16(
    float* c, const unsigned* a, unsigned b0, unsigned b1)
{
    asm volatile(
        "mma.sync.aligned.m16n8k16.row.col.f32.f16.f16.f32 "
        "{%0,%1,%2,%3}, {%4,%5,%6,%7}, {%8,%9}, {%0,%1,%2,%3};"
        : "+f"(c[0]), "+f"(c[1]), "+f"(c[2]), "+f"(c[3])
        : "r"(a[0]), "r"(a[1]), "r"(a[2]), "r"(a[3]),
          "r"(b0), "r"(b1));
}

__device__ __forceinline__ void ldsm4(unsigned* r, uint32_t addr) {
    asm volatile(
        "ldmatrix.sync.aligned.m8n8.x4.shared.b16 {%0,%1,%2,%3}, [%4];"
        : "=r"(r[0]), "=r"(r[1]), "=r"(r[2]), "=r"(r[3]) : "r"(addr));
}

__device__ __forceinline__ void cp16(unsigned smem, const void* g) {
    asm volatile("cp.async.cg.shared.global [%0], [%1], 16;\n" :: "r"(smem), "l"(g));
}
__device__ __forceinline__ void cp_commit() {
    asm volatile("cp.async.commit_group;\n");
}
template<int N> __device__ __forceinline__ void cp_wait() {
    asm volatile("cp.async.wait_group %0;\n" :: "n"(N));
}

// ---------------- convert kernels (fp32 -> fp16) ----------------------------
__global__ __launch_bounds__(256) void tohalf_kernel(
    const float* __restrict__ src, __half* __restrict__ dst, int n)
{
    int i = blockIdx.x * 256 + threadIdx.x;
    if (i < n) dst[i] = __float2half(src[i]);
}
__global__ __launch_bounds__(256) void tohalf_pad_kernel(
    const float* __restrict__ src, __half* __restrict__ dst, int rows, int rows_pad, int cols)
{
    int i = blockIdx.x * 256 + threadIdx.x;
    if (i < rows_pad * cols) {
        int r = i / cols;
        dst[i] = (r < rows) ? __float2half(src[i]) : __float2half(0.f);
    }
}

// ---------------- persistent pipelined fp16 NT GEMM -------------------------
#define STAGES 3
#define SSTRIDE_H (128*64)
#define GEMM_THREADS 128
__global__ __launch_bounds__(GEMM_THREADS, 2) void gemm_f16_pipe(
    const __half* __restrict__ A, const __half* __restrict__ B, float* __restrict__ C,
    int M, int N, int K, int lda, int ldb, int ldc)
{
    extern __shared__ __half smh[];
    __half* As = smh;
    __half* Bs = smh + STAGES * SSTRIDE_H;
    int tid = threadIdx.x;
    int warp = tid >> 5, lane = tid & 31;
    int g = lane >> 2, tg = lane & 3;
    int wm = (warp & 1) * 64, wn = (warp >> 1) * 64;

    int grp = lane >> 3, rin = lane & 7;
    int rowF = (grp & 1) * 8 + rin;
    int bitF = grp >> 1;

    unsigned asBase = (unsigned)__cvta_generic_to_shared(As);
    unsigned bsBase = (unsigned)__cvta_generic_to_shared(Bs);

    const int KT = K >> 6;
    const int ntn = (N + 127) >> 7;
    const int ntiles = (M >> 7) * ntn;

    for (int tile = blockIdx.x; tile < ntiles; tile += gridDim.x) {
        int bm = (tile / ntn) * 128;
        int bn = (tile % ntn) * 128;

        float acc[4][8][4];
#pragma unroll
        for (int mi = 0; mi < 4; mi++)
#pragma unroll
            for (int ni = 0; ni < 8; ni++)
#pragma unroll
                for (int j = 0; j < 4; j++) acc[mi][ni][j] = 0.f;

        auto issue_stage = [&](int stage, int kt) {
            int kk = kt << 6;
            unsigned aS = asBase + (unsigned)(stage * SSTRIDE_H) * 2u;
            unsigned bS = bsBase + (unsigned)(stage * SSTRIDE_H) * 2u;
#pragma unroll
            for (int i = 0; i < 8; i++) {
                int id = tid + i * GEMM_THREADS;
                int row = id >> 3, c16 = id & 7;
                int pc = c16 ^ (row & 7);
                unsigned off = (unsigned)(row * 128 + pc * 16);
                cp16(aS + off, A + (size_t)(bm + row) * lda + kk + c16 * 8);
                cp16(bS + off, B + (size_t)(bn + row) * ldb + kk + c16 * 8);
            }
            cp_commit();
        };

        issue_stage(0, 0);
        if (KT > 1) issue_stage(1, 1);

        for (int kt = 0; kt < KT; kt++) {
            if (kt < KT - 1) cp_wait<1>(); else cp_wait<0>();
            __syncthreads();
            if (kt + 2 < KT) issue_stage((kt + 2) % STAGES, kt + 2);

            unsigned aS = asBase + (unsigned)((kt % STAGES) * SSTRIDE_H) * 2u;
            unsigned bS = bsBase + (unsigned)((kt % STAGES) * SSTRIDE_H) * 2u;
#pragma unroll
            for (int ks = 0; ks < 4; ks++) {
                unsigned af[4][4], bf[4][4];
#pragma unroll
                for (int mi = 0; mi < 4; mi++) {
                    unsigned addr = aS
                        + (unsigned)((wm + mi * 16 + rowF) * 128)
                        + (unsigned)((((2*ks + bitF) ^ rin) & 7) << 4);
                    ldsm4(af[mi], addr);
                }
#pragma unroll
                for (int np = 0; np < 4; np++) {
                    unsigned addr = bS
                        + (unsigned)((wn + np * 16 + rowF) * 128)
                        + (unsigned)((((2*ks + bitF) ^ rin) & 7) << 4);
                    ldsm4(bf[np], addr);
                }
#pragma unroll
                for (int mi = 0; mi < 4; mi++) {
#pragma unroll
                    for (int np = 0; np < 4; np++) {
                        mma_f16(acc[mi][np*2    ], af[mi], bf[np][0], bf[np][2]);
                        mma_f16(acc[mi][np*2 + 1], af[mi], bf[np][1], bf[np][3]);
                    }
                }
            }
        }

#pragma unroll
        for (int mi = 0; mi < 4; mi++) {
            int row0 = bm + wm + mi * 16 + g;
#pragma unroll
            for (int ni = 0; ni < 8; ni++) {
                int col = bn + wn + ni * 8 + 2 * tg;
                if (col < N) {
                    *(float2*)(C + (size_t)row0 * ldc + col) =
                        make_float2(acc[mi][ni][0], acc[mi][ni][1]);
                    *(float2*)(C + (size_t)(row0 + 8) * ldc + col) =
                        make_float2(acc[mi][ni][2], acc[mi][ni][3]);
                }
            }
        }
        __syncthreads();
    }
}

// -------- smem-tiled causal depthwise conv (K=4) + bias + SiLU -------------
#define CVT 256
__global__ __launch_bounds__(256) void conv_silu_kernel(
    const float* __restrict__ cw, const float* __restrict__ cb)
{
    extern __shared__ float sh[];          // [(CVT+3)][68]
    int tid = threadIdx.x;
    int c0 = blockIdx.x * 64;
    int l0 = blockIdx.y * CVT;
    int b  = blockIdx.z;

    for (int idx = tid; idx < (CVT + 3) * 64; idx += 256) {
        int r = idx >> 6, c = idx & 63;
        int gl = l0 + r - 3;
        float v = 0.f;
        if (gl >= 0)
            v = g_proj[((size_t)(b*L_SEQ + gl))*PROJ + D_INNER + c0 + c];
        sh[r*68 + c] = v;
    }
    __syncthreads();

    int c = tid & 63, lg = tid >> 6;
    int ch = c0 + c;
    float w0 = cw[ch*4 + 0], w1 = cw[ch*4 + 1];
    float w2 = cw[ch*4 + 2], w3 = cw[ch*4 + 3];
    float bias = cb[ch];
#pragma unroll 4
    for (int i = 0; i < 64; i++) {
        int l = lg*64 + i;
        const float* r = sh + l*68 + c;
        float acc = bias + r[0]*w0 + r[68]*w1 + r[136]*w2 + r[204]*w3;
        acc = acc / (1.f + __expf(-acc));
        g_xc[((size_t)(b*L_SEQ + l0 + l))*CONV_DIM + ch] = acc;
    }
}

// ------- dt softplus + per-64-chunk inclusive cumsum of dt*A ---------------
// g_dtsp layout: [b][h][l]  (coalesced write here, coalesced read in chunk_fwd)
__global__ __launch_bounds__(256) void dtscan_kernel(
    const float* __restrict__ dt_bias, const float* __restrict__ A_log)
{
    __shared__ float s[256];
    int z = blockIdx.x;
    int q = z & 7, h = (z >> 3) & 63, b = z >> 9;
    int t = threadIdx.x;
    int gl = q*256 + t;
    float raw = g_proj[((size_t)(b*L_SEQ + gl))*PROJ + D_INNER + CONV_DIM + h] + dt_bias[h];
    float dts = (raw > 20.f) ? raw : log1pf(__expf(raw));
    g_dtsp[((size_t)(b*NH + h))*L_SEQ + gl] = dts;
    s[t] = -dts * __expf(A_log[h]);
    __syncthreads();
    for (int off = 1; off < 64; off <<= 1) {
        float v = ((t & 63) >= off) ? s[t - off] : 0.f;
        __syncthreads();
        s[t] += v;
        __syncthreads();
    }
    int c = gl >> 6;
    g_Acum[((size_t)((b*NH + h)*NC + c))*CS + (gl & 63)] = s[t];
}

// -------- G[l][s] = C[l]·B[s] per (b,chunk), tf32 mma ----------------------
__global__ __launch_bounds__(256) void gt_kernel()
{
    extern __shared__ float smg[];
    float* Ct = smg;              // [64][132]
    float* Bt = smg + 64*132;
    int z = blockIdx.x;
    int c = z & 31, b = z >> 5;
    int tid = threadIdx.x;
    size_t t0 = (size_t)(b*L_SEQ + c*CS);
    {
        int n = tid & 127, rg = tid >> 7;
#pragma unroll
        for (int i = 0; i < 32; i++) {
            int row = rg*32 + i;
            Bt[row*132 + n] = f2tf(g_xc[(t0 + row)*CONV_DIM + D_INNER + n]);
            Ct[row*132 + n] = f2tf(g_xc[(t0 + row)*CONV_DIM + D_INNER + NDIM + n]);
        }
    }
    __syncthreads();

    int warp = tid >> 5, lane = tid & 31;
    int g = lane >> 2, tg = lane & 3;
    int wm = (warp & 3) * 16;
    int wn = (warp >> 2) * 32;

    float acc[4][4];
#pragma unroll
    for (int ni = 0; ni < 4; ni++)
#pragma unroll
        for (int j = 0; j < 4; j++) acc[ni][j] = 0.f;

#pragma unroll
    for (int ks = 0; ks < 16; ks++) {
        int k0 = ks*8 + tg;
        unsigned a[4];
        a[0] = __float_as_uint(Ct[(wm + g    )*132 + k0    ]);
        a[1] = __float_as_uint(Ct[(wm + g + 8)*132 + k0    ]);
        a[2] = __float_as_uint(Ct[(wm + g    )*132 + k0 + 4]);
        a[3] = __float_as_uint(Ct[(wm + g + 8)*132 + k0 + 4]);
#pragma unroll
        for (int ni = 0; ni < 4; ni++) {
            unsigned bb[2];
            bb[0] = __float_as_uint(Bt[(wn + ni*8 + g)*132 + k0    ]);
            bb[1] = __float_as_uint(Bt[(wn + ni*8 + g)*132 + k0 + 4]);
            mma_tf32(acc[ni], a, bb);
        }
    }

    float* gout = g_Gt + (size_t)(b*NC + c)*CS*CS;
#pragma unroll
    for (int ni = 0; ni < 4; ni++) {
        int col = wn + ni*8 + 2*tg;
        *(float2*)(gout + (wm + g    )*CS + col) = make_float2(acc[ni][0], acc[ni][1]);
        *(float2*)(gout + (wm + g + 8)*CS + col) = make_float2(acc[ni][2], acc[ni][3]);
    }
}

// ---------------- fused chunk forward: Y_diag (+D*x) and states (fp16) -----
__global__ __launch_bounds__(256) void chunk_fwd_kernel(const float* __restrict__ Dp)
{
    extern __shared__ float smc[];
    float* XdtT = smc;             // [64][68]
    float* W    = smc + 64*68;     // [64][68]
    float* BT   = smc + 2*64*68;   // [128][68]
    float* Acs  = smc + 2*64*68 + 128*68;
    float* dts  = Acs + 64;
    float* dec  = dts + 64;

    int z = blockIdx.x;
    int h = z & 63, c = (z >> 6) & 31, b = z >> 11;
    int tid = threadIdx.x;
    size_t t0 = (size_t)(b*L_SEQ + c*CS);

    if (tid < 64) {
        Acs[tid] = g_Acum[((size_t)((b*NH + h)*NC + c))*CS + tid];
        dts[tid] = g_dtsp[((size_t)(b*NH + h))*L_SEQ + c*CS + tid];
    }
    __syncthreads();
    if (tid < 64) dec[tid] = __expf(Acs[63] - Acs[tid]);

    {
        int p = tid & 63, lg = tid >> 6;
#pragma unroll
        for (int i = 0; i < 16; i++) {
            int l = lg*16 + i;
            float v = g_xc[(t0 + l)*CONV_DIM + h*64 + p] * dts[l];
            XdtT[p*68 + l] = f2tf(v);
        }
    }
    {
        int l = tid >> 2, sb = tid & 3;
        const float* grow = g_Gt + (size_t)(b*NC + c)*CS*CS + l*CS;
        float al = Acs[l];
        float dg = Dp[h] / fmaxf(dts[l], 1e-30f);
#pragma unroll
        for (int i = 0; i < 16; i++) {
            int s = sb*16 + i;
            float wv;
            if (s < l)       wv = f2tf(grow[s] * __expf(al - Acs[s]));
            else if (s == l) wv = f2tf(grow[s] + dg);
            else             wv = 0.f;
            W[l*68 + s] = wv;
        }
    }
    __syncthreads();
    {
        int n = tid & 127, lg = tid >> 7;
#pragma unroll
        for (int i = 0; i < 32; i++) {
            int l = lg*32 + i;
            float v = g_xc[(t0 + l)*CONV_DIM + D_INNER + n] * dec[l];
            BT[n*68 + l] = f2tf(v);
        }
    }
    __syncthreads();

    int warp = tid >> 5, lane = tid & 31;
    int g = lane >> 2, tg = lane & 3;

    {
        int wm = (warp & 3) * 16, wn = (warp >> 2) * 32;
        float acc[4][4];
#pragma unroll
        for (int ni = 0; ni < 4; ni++)
#pragma unroll
            for (int j = 0; j < 4; j++) acc[ni][j] = 0.f;
#pragma unroll
        for (int ks = 0; ks < 8; ks++) {
            int k0 = ks*8 + tg;
            unsigned a[4];
            a[0] = __float_as_uint(W[(wm + g    )*68 + k0    ]);
            a[1] = __float_as_uint(W[(wm + g + 8)*68 + k0    ]);
            a[2] = __float_as_uint(W[(wm + g    )*68 + k0 + 4]);
            a[3] = __float_as_uint(W[(wm + g + 8)*68 + k0 + 4]);
#pragma unroll
            for (int ni = 0; ni < 4; ni++) {
                unsigned bb[2];
                bb[0] = __float_as_uint(XdtT[(wn + ni*8 + g)*68 + k0    ]);
                bb[1] = __float_as_uint(XdtT[(wn + ni*8 + g)*68 + k0 + 4]);
                mma_tf32(acc[ni], a, bb);
            }
        }
        int r0 = wm + g, r1 = wm + g + 8;
#pragma unroll
        for (int ni = 0; ni < 4; ni++) {
            int col = wn + ni*8 + 2*tg;
            *(float2*)(g_y + (t0 + r0)*D_INNER + h*64 + col) =
                make_float2(acc[ni][0], acc[ni][1]);
            *(float2*)(g_y + (t0 + r1)*D_INNER + h*64 + col) =
                make_float2(acc[ni][2], acc[ni][3]);
        }
    }

    {
        int wm = (warp & 3) * 16, wn = (warp >> 2) * 64;
        float acc[8][4];
#pragma unroll
        for (int ni = 0; ni < 8; ni++)
#pragma unroll
            for (int j = 0; j < 4; j++) acc[ni][j] = 0.f;
#pragma unroll
        for (int ks = 0; ks < 8; ks++) {
            int k0 = ks*8 + tg;
            unsigned a[4];
            a[0] = __float_as_uint(XdtT[(wm + g    )*68 + k0    ]);
            a[1] = __float_as_uint(XdtT[(wm + g + 8)*68 + k0    ]);
            a[2] = __float_as_uint(XdtT[(wm + g    )*68 + k0 + 4]);
            a[3] = __float_as_uint(XdtT[(wm + g + 8)*68 + k0 + 4]);
#pragma unroll
            for (int ni = 0; ni < 8; ni++) {
                unsigned bb[2];
                bb[0] = __float_as_uint(BT[(wn + ni*8 + g)*68 + k0    ]);
                bb[1] = __float_as_uint(BT[(wn + ni*8 + g)*68 + k0 + 4]);
                mma_tf32(acc[ni], a, bb);
            }
        }
        __half* sb = g_states + ((size_t)((b*NC + c)*NH + h))*PDIM*NDIM;
        int r0 = wm + g, r1 = wm + g + 8;
#pragma unroll
        for (int ni = 0; ni < 8; ni++) {
            int col = wn + ni*8 + 2*tg;
            *(__half2*)(sb + (size_t)r0*NDIM + col) =
                __floats2half2_rn(acc[ni][0], acc[ni][1]);
            *(__half2*)(sb + (size_t)r1*NDIM + col) =
                __floats2half2_rn(acc[ni][2], acc[ni][3]);
        }
    }
}

// ---------------- inter-chunk scan (fp32 carry, fp16 storage, half2) -------
__global__ __launch_bounds__(256) void scan_kernel()
{
    int idx = blockIdx.x * 256 + threadIdx.x;   // over B*NH*P*N/2 = 524288
    int n2 = idx & 63;                          // half2 index (2 n per thread)
    int p = (idx >> 6) & 63;
    int h = (idx >> 12) & 63;
    int b = idx >> 18;
    float2 carry = make_float2(0.f, 0.f);
    for (int c = 0; c < NC; c++) {
        size_t off2 = (((size_t)((b*NC + c)*NH + h))*PDIM*NDIM + (size_t)p*NDIM) / 2 + n2;
        float dal = g_Acum[((size_t)((b*NH + h)*NC + c))*CS + (CS-1)];
        float2 s = __half22float2(((const __half2*)g_states)[off2]);
        ((__half2*)g_prev)[off2] = __floats2half2_rn(carry.x, carry.y);
        float e = __expf(dal);
        carry.x = carry.x * e + s.x;
        carry.y = carry.y * e + s.y;
    }
}

// ---------------- inter-chunk contribution (tf32 mma) -----------------------
__global__ __launch_bounds__(256) void yoff_kernel()
{
    extern __shared__ float smo[];
    float* Cs  = smo;             // [64][132] tf32, n fast
    float* Pv  = smo + 64*132;    // [64][132] prev[p][n] tf32
    float* Acs = smo + 2*64*132;  // [64]
    int z = blockIdx.x;
    int h = z & 63, c = (z >> 6) & 31, b = z >> 11;
    int tid = threadIdx.x;
    size_t t0 = (size_t)(b*L_SEQ + c*CS);

    if (tid < 64) Acs[tid] = g_Acum[((size_t)((b*NH + h)*NC + c))*CS + tid];
    {
        int n = tid & 127, rg = tid >> 7;
        const __half* pb = g_prev + ((size_t)((b*NC + c)*NH + h))*PDIM*NDIM;
#pragma unroll
        for (int i = 0; i < 32; i++) {
            int row = rg*32 + i;
            Cs[row*132 + n] = f2tf(g_xc[(t0 + row)*CONV_DIM + D_INNER + NDIM + n]);
            Pv[row*132 + n] = f2tf(__half2float(pb[(size_t)row*NDIM + n]));
        }
    }
    __syncthreads();

    int warp = tid >> 5, lane = tid & 31;
    int g = lane >> 2, tg = lane & 3;
    int wm = (warp & 3) * 16;
    int wn = (warp >> 2) * 32;

    float acc[4][4];
#pragma unroll
    for (int ni = 0; ni < 4; ni++)
#pragma unroll
        for (int j = 0; j < 4; j++) acc[ni][j] = 0.f;

#pragma unroll
    for (int ks = 0; ks < 16; ks++) {
        int k0 = ks*8 + tg;
        unsigned a[4];
        a[0] = __float_as_uint(Cs[(wm + g    )*132 + k0    ]);
        a[1] = __float_as_uint(Cs[(wm + g + 8)*132 + k0    ]);
        a[2] = __float_as_uint(Cs[(wm + g    )*132 + k0 + 4]);
        a[3] = __float_as_uint(Cs[(wm + g + 8)*132 + k0 + 4]);
#pragma unroll
        for (int ni = 0; ni < 4; ni++) {
            unsigned bb[2];
            bb[0] = __float_as_uint(Pv[(wn + ni*8 + g)*132 + k0    ]);
            bb[1] = __float_as_uint(Pv[(wn + ni*8 + g)*132 + k0 + 4]);
            mma_tf32(acc[ni], a, bb);
        }
    }

    float e0 = __expf(Acs[wm + g]);
    float e1 = __expf(Acs[wm + g + 8]);
#pragma unroll
    for (int ni = 0; ni < 4; ni++) {
        int col = wn + ni*8 + 2*tg;
        float* y0 = g_y + (t0 + wm + g)*D_INNER + h*64 + col;
        float* y1 = g_y + (t0 + wm + g + 8)*D_INNER + h*64 + col;
        float2 v0 = *(float2*)y0;
        float2 v1 = *(float2*)y1;
        v0.x += e0*acc[ni][0]; v0.y += e0*acc[ni][1];
        v1.x += e1*acc[ni][2]; v1.y += e1*acc[ni][3];
        *(float2*)y0 = v0;
        *(float2*)y1 = v1;
    }
}

// ---------------- gated RMSNorm (writes fp16 output for out-proj) ----------
__global__ __launch_bounds__(256) void norm_kernel(const float* __restrict__ norm_w)
{
    __shared__ float gs[D_INNER];
    __shared__ float red[8];
    int t = blockIdx.x;
    int tid = threadIdx.x;
    const float* zrow = g_proj + (size_t)t * PROJ;
    const float* yrow = g_y + (size_t)t * D_INNER;
    __half* orow = g_yh + (size_t)t * D_INNER;
    float sum = 0.f;
    for (int i = tid; i < D_INNER; i += 256) {
        float zv = zrow[i];
        float g = yrow[i] * (zv / (1.f + __expf(-zv)));
        gs[i] = g;
        sum += g*g;
    }
#pragma unroll
    for (int o = 16; o; o >>= 1) sum += __shfl_xor_sync(0xffffffffu, sum, o);
    if ((tid & 31) == 0) red[tid >> 5] = sum;
    __syncthreads();
    if (tid < 8) {
        float v = red[tid];
#pragma unroll
        for (int o = 4; o; o >>= 1) v += __shfl_xor_sync(0xffu, v, o);
        if (tid == 0) red[0] = v;
    }
    __syncthreads();
    float r = rsqrtf(red[0] / (float)D_INNER + 1e-5f);
    for (int i = tid; i < D_INNER; i += 256)
        orow[i] = __float2half(gs[i] * r * norm_w[i]);
}

// ---------------- launch ---------------------------------------------------
extern "C" void kernel_launch(void* const* d_in, const int* in_sizes, int n_in,
                              void* d_out, int out_size)
{
    const float* hs      = (const float*)d_in[0];
    const float* W_in    = (const float*)d_in[1];
    const float* conv_w  = (const float*)d_in[2];
    const float* conv_b  = (const float*)d_in[3];
    const float* dt_bias = (const float*)d_in[4];
    const float* A_log   = (const float*)d_in[5];
    const float* Dp      = (const float*)d_in[6];
    const float* norm_w  = (const float*)d_in[7];
    const float* W_out   = (const float*)d_in[8];
    float* out = (float*)d_out;

    float *proj;
    __half *hsh, *Wih, *Woh, *yh;
    cudaGetSymbolAddress((void**)&proj, g_proj);
    cudaGetSymbolAddress((void**)&hsh,  g_hsh);
    cudaGetSymbolAddress((void**)&Wih,  g_Wih);
    cudaGetSymbolAddress((void**)&Woh,  g_Woh);
    cudaGetSymbolAddress((void**)&yh,   g_yh);

    const int gemmsm  = STAGES * 2 * SSTRIDE_H * (int)sizeof(__half);       // 98,304 B
    const int convsm  = (CVT + 3) * 68 * (int)sizeof(float);                // 70,448 B
    const int gtsm    = 2 * 64 * 132 * (int)sizeof(float);                  // 67,584 B
    const int chunksm = (2*64*68 + 128*68 + 3*64) * (int)sizeof(float);
    const int yoffsm  = (2*64*132 + 64) * (int)sizeof(float);
    cudaFuncSetAttribute(gemm_f16_pipe,    cudaFuncAttributeMaxDynamicSharedMemorySize, gemmsm);
    cudaFuncSetAttribute(conv_silu_kernel, cudaFuncAttributeMaxDynamicSharedMemorySize, convsm);
    cudaFuncSetAttribute(gt_kernel,        cudaFuncAttributeMaxDynamicSharedMemorySize, gtsm);
    cudaFuncSetAttribute(chunk_fwd_kernel, cudaFuncAttributeMaxDynamicSharedMemorySize, chunksm);
    cudaFuncSetAttribute(yoff_kernel,      cudaFuncAttributeMaxDynamicSharedMemorySize, yoffsm);

    const int M = NBATCH * L_SEQ;   // 4096 tokens
    const int NBLK = 296;           // persistent grid

    // 0) convert operands to fp16
    {
        int n1 = M * HIDDEN;
        tohalf_kernel<<<(n1 + 255)/256, 256>>>(hs, hsh, n1);
        int n2 = PROJ_PAD * HIDDEN;
        tohalf_pad_kernel<<<(n2 + 255)/256, 256>>>(W_in, Wih, PROJ, PROJ_PAD, HIDDEN);
        int n3 = HIDDEN * D_INNER;
        tohalf_kernel<<<(n3 + 255)/256, 256>>>(W_out, Woh, n3);
    }

    // 1) in-proj
    gemm_f16_pipe<<<NBLK, GEMM_THREADS, gemmsm>>>(
        hsh, Wih, proj, M, PROJ, HIDDEN, HIDDEN, HIDDEN, PROJ);

    // 2) causal conv + SiLU (smem-tiled)
    conv_silu_kernel<<<dim3(CONV_DIM/64, L_SEQ/CVT, NBATCH), 256, convsm>>>(conv_w, conv_b);

    // 3) dt softplus + per-64-chunk cumsum (transposed dtsp)
    dtscan_kernel<<<NBATCH*NH*8, 256>>>(dt_bias, A_log);

    // 4) G[l][s] per (b,chunk) (tf32 mma)
    gt_kernel<<<NBATCH*NC, 256, gtsm>>>();

    // 5) fused Y_diag (+D*x) and per-chunk states (fp16 states)
    chunk_fwd_kernel<<<NBATCH*NC*NH, 256, chunksm>>>(Dp);

    // 6) inter-chunk scan (fp32 carry, fp16 storage, half2)
    scan_kernel<<<(NBATCH*NH*PDIM*NDIM/2)/256, 256>>>();

    // 7) inter-chunk contribution (tf32 mma, 4096 blocks)
    yoff_kernel<<<NBATCH*NC*NH, 256, yoffsm>>>();

    // 8) gated RMSNorm (emits fp16 y)
    norm_kernel<<<M, 256>>>(norm_w);

    // 9) out-proj
    gemm_f16_pipe<<<NBLK, GEMM_THREADS, gemmsm>>>(
        yh, Woh, out, M, HIDDEN, D_INNER, D_INNER, D_INNER, HIDDEN);
}